// round 9
// baseline (speedup 1.0000x reference)
#include <cuda_runtime.h>
#include <cuda_fp16.h>
#include <cstdint>

#define D_MODEL 2048
#define N_HEADS 16
#define D_HEAD  128
#define SEQ     2048
#define BATCH   2
#define BS      (BATCH * SEQ)      // 4096
#define QKV_N   (3 * D_MODEL)      // 6144

// Scratch (allocation-free rule: __device__ globals) — fp16
__device__ __half g_qkv[(size_t)BS * QKV_N];          // 48 MB
__device__ __half g_att[(size_t)BS * D_MODEL];        // 16 MB
__device__ __half g_xh[(size_t)BS * D_MODEL];         // 16 MB
__device__ __half g_wqkvT[(size_t)QKV_N * D_MODEL];   // 24 MB
__device__ __half g_woutT[(size_t)D_MODEL * D_MODEL]; // 8 MB

__device__ __forceinline__ uint32_t smem_u32(const void* p) {
    uint32_t a;
    asm("{ .reg .u64 t; cvta.to.shared.u64 t, %1; cvt.u32.u64 %0, t; }" : "=r"(a) : "l"(p));
    return a;
}

// fp16 mma, fp32 accumulate: D(16x8) += A(16x16) x B(16x8)
__device__ __forceinline__ void mma16(float d[4], const uint32_t a[4], const uint32_t b[2]) {
    asm volatile(
        "mma.sync.aligned.m16n8k16.row.col.f32.f16.f16.f32 "
        "{%0,%1,%2,%3}, {%4,%5,%6,%7}, {%8,%9}, {%0,%1,%2,%3};\n"
        : "+f"(d[0]), "+f"(d[1]), "+f"(d[2]), "+f"(d[3])
        : "r"(a[0]), "r"(a[1]), "r"(a[2]), "r"(a[3]), "r"(b[0]), "r"(b[1]));
}

#define LDSM4(R0, R1, R2, R3, ADDR) \
    asm volatile("ldmatrix.sync.aligned.m8n8.x4.shared.b16 {%0,%1,%2,%3}, [%4];" \
                 : "=r"(R0), "=r"(R1), "=r"(R2), "=r"(R3) : "r"(ADDR))

__device__ __forceinline__ void cpasync16(uint32_t dst, const void* src) {
    asm volatile("cp.async.cg.shared.global [%0], [%1], 16;" :: "r"(dst), "l"(src) : "memory");
}
__device__ __forceinline__ void cp_commit() {
    asm volatile("cp.async.commit_group;" ::: "memory");
}
__device__ __forceinline__ void cp_wait0() {
    asm volatile("cp.async.wait_group 0;" ::: "memory");
}
__device__ __forceinline__ void cp_wait1() {
    asm volatile("cp.async.wait_group 1;" ::: "memory");
}

__device__ __forceinline__ uint32_t packh2(float a, float b) {
    __half2 h = __floats2half2_rn(a, b);
    return *(uint32_t*)&h;
}

// ============================================================================
// Prep kernels: fp32 -> fp16 convert, and transpose-convert for weights.
// ============================================================================
__global__ void conv_half(const float* __restrict__ in, __half* __restrict__ out, int n4) {
    int i = blockIdx.x * blockDim.x + threadIdx.x;
    if (i < n4) {
        float4 v = ((const float4*)in)[i];
        __half2* o = (__half2*)(out) + i * 2;
        o[0] = __floats2half2_rn(v.x, v.y);
        o[1] = __floats2half2_rn(v.z, v.w);
    }
}

// W [K][N] fp32 -> Wt [N][K] fp16
__global__ void transpose_half(const float* __restrict__ W, __half* __restrict__ Wt,
                               int K, int N) {
    __shared__ float t[32][33];
    int n0 = blockIdx.x * 32, k0 = blockIdx.y * 32;
    int tx = threadIdx.x, ty = threadIdx.y;
#pragma unroll
    for (int i = ty; i < 32; i += 8)
        t[i][tx] = W[(size_t)(k0 + i) * N + n0 + tx];
    __syncthreads();
#pragma unroll
    for (int i = ty; i < 32; i += 8)
        Wt[(size_t)(n0 + i) * K + k0 + tx] = __float2half(t[tx][i]);
}

// ============================================================================
// fp16 GEMM (unchanged from R8 — at legacy-mma f32-accum ceiling):
// C[M,N] = A[M,K] @ Bt[N,K]^T + bias[N]
// Block 128x128, 8 warps (4x2), warp tile 32x64, K-slab 64 halfs, 3-stage ring.
// ============================================================================
#define G_LDS 72
#define G_TILE_BYTES (128 * G_LDS * 2)              // 18432 per operand
#define G_STAGE_BYTES (2u * G_TILE_BYTES)           // 36864
#define G_SMEM_BYTES (3u * G_STAGE_BYTES)           // 110592

__global__ __launch_bounds__(256, 2) void gemm_h(
    const __half* __restrict__ A, const __half* __restrict__ Bt,
    const float* __restrict__ bias, float* __restrict__ Cf, __half* __restrict__ Ch,
    int M, int N, int K, int store_half)
{
    extern __shared__ __half smem[];
    const uint32_t sbase = smem_u32(smem);

    const int tid  = threadIdx.x;
    const int lane = tid & 31;
    const int wid  = tid >> 5;
    const int wm   = wid >> 1;
    const int wn   = wid & 1;
    const int g    = lane >> 2;
    const int tig  = lane & 3;

    const int m0 = blockIdx.y * 128;
    const int n0 = blockIdx.x * 128;
    const __half* Ag = A + (size_t)m0 * K;
    const __half* Bg = Bt + (size_t)n0 * K;
    const int nslab = K >> 6;

    const int crow = tid >> 3;
    const int ccj  = (tid & 7) * 8;

    const int lmrow = lane & 15;
    const uint32_t lmc16 = (lane >> 4) * 16;
    const uint32_t a_lm = sbase + (wm * 32 + lmrow) * 144 + lmc16;
    const uint32_t b_lm = sbase + (uint32_t)G_TILE_BYTES + (wn * 64 + lmrow) * 144 + lmc16;

    float acc[2][8][4];
#pragma unroll
    for (int mt = 0; mt < 2; mt++)
#pragma unroll
        for (int nt = 0; nt < 8; nt++)
#pragma unroll
            for (int i = 0; i < 4; i++) acc[mt][nt][i] = 0.f;

    auto load_slab = [&](int i, int s) {
        const uint32_t ab = sbase + (uint32_t)s * G_STAGE_BYTES;
        const uint32_t bb = ab + (uint32_t)G_TILE_BYTES;
        const int k0 = i << 6;
#pragma unroll
        for (int r = 0; r < 4; r++) {
            int row = crow + r * 32;
            cpasync16(ab + row * 144 + ccj * 2, Ag + (size_t)row * K + k0 + ccj);
        }
#pragma unroll
        for (int r = 0; r < 4; r++) {
            int row = crow + r * 32;
            cpasync16(bb + row * 144 + ccj * 2, Bg + (size_t)row * K + k0 + ccj);
        }
        cp_commit();
    };

    load_slab(0, 0);
    load_slab(1, 1);

    int s_c = 0;
    int s_l = 2;
    for (int i = 0; i < nslab; i++) {
        cp_wait1();
        __syncthreads();
        if (i + 2 < nslab) load_slab(i + 2, s_l);
        else cp_commit();

        const uint32_t a_st = a_lm + (uint32_t)s_c * G_STAGE_BYTES;
        const uint32_t b_st = b_lm + (uint32_t)s_c * G_STAGE_BYTES;
#pragma unroll
        for (int ks = 0; ks < 4; ks++) {
            const uint32_t ka = a_st + ks * 32;
            uint32_t af0[4], af1[4];
            LDSM4(af0[0], af0[1], af0[2], af0[3], ka);
            LDSM4(af1[0], af1[1], af1[2], af1[3], ka + 2304);
            const uint32_t kb = b_st + ks * 32;
#pragma unroll
            for (int q = 0; q < 4; q++) {
                uint32_t b0, b1, b2, b3;
                LDSM4(b0, b1, b2, b3, kb + q * 2304);
                uint32_t bfA[2] = { b0, b2 };
                uint32_t bfB[2] = { b1, b3 };
                mma16(acc[0][2 * q],     af0, bfA);
                mma16(acc[0][2 * q + 1], af0, bfB);
                mma16(acc[1][2 * q],     af1, bfA);
                mma16(acc[1][2 * q + 1], af1, bfB);
            }
        }
        s_c++; if (s_c == 3) s_c = 0;
        s_l++; if (s_l == 3) s_l = 0;
    }

#pragma unroll
    for (int mt = 0; mt < 2; mt++) {
        int r = m0 + wm * 32 + mt * 16 + g;
#pragma unroll
        for (int nt = 0; nt < 8; nt++) {
            int c = n0 + wn * 64 + nt * 8 + tig * 2;
            float b0 = bias[c], b1 = bias[c + 1];
            float v0 = acc[mt][nt][0] + b0;
            float v1 = acc[mt][nt][1] + b1;
            float v2 = acc[mt][nt][2] + b0;
            float v3 = acc[mt][nt][3] + b1;
            if (store_half) {
                *(__half2*)(Ch + (size_t)r * N + c)       = __floats2half2_rn(v0, v1);
                *(__half2*)(Ch + (size_t)(r + 8) * N + c) = __floats2half2_rn(v2, v3);
            } else {
                *(float2*)(Cf + (size_t)r * N + c)       = make_float2(v0, v1);
                *(float2*)(Cf + (size_t)(r + 8) * N + c) = make_float2(v2, v3);
            }
        }
    }
}

// ============================================================================
// Flash attention (causal), fp16 mma.
// R9: P stays in registers (S-accum layout == A-fragment layout), Vst double-
// buffered, ONE __syncthreads per kv-tile, 2 CTAs/SM, LPT (big q-tiles first).
// ============================================================================
#define LDQh 136   // Q/K row stride in halfs (272 B)
#define LDVh 72    // Vst row stride in halfs (144 B)
// Q 128*136 + K 2*64*136 + V 2*128*72 halfs = 53248 halfs = 106496 B
#define ATTN_SMEM_BYTES ((128 * LDQh + 128 * LDQh + 256 * LDVh) * 2)

__global__ __launch_bounds__(256, 2) void attn_kernel(
    const __half* __restrict__ qkv, __half* __restrict__ out)
{
    extern __shared__ __half smh[];
    __half* Vst = smh + 256 * LDQh;         // 2 x [128][72] (row=d, col=kv)

    const int tid  = threadIdx.x;
    const int lane = tid & 31;
    const int wid  = tid >> 5;
    const int g    = lane >> 2;
    const int tig  = lane & 3;
    const int rbase = wid * 16;
    const int r1 = rbase + g;
    const int r2 = r1 + 8;

    const int qt = (int)gridDim.x - 1 - (int)blockIdx.x;   // LPT: largest first
    const int h  = blockIdx.y;
    const int b  = blockIdx.z;
    const int q0 = qt * 128;

    const float scale = 0.08838834764831845f; // 1/sqrt(128)
    const __half* Qg = qkv + (size_t)b * SEQ * QKV_N + h * D_HEAD;
    const __half* Kg = Qg + D_MODEL;
    const __half* Vg = Qg + 2 * D_MODEL;

    const int lmrow = lane & 15;
    const uint32_t lmc16 = (lane >> 4) * 16;
    const uint32_t sb = smem_u32(smh);
    const uint32_t q_lm  = sb + (rbase + lmrow) * 272 + lmc16;
    const uint32_t k_lm0 = sb + 128 * 272 + lmrow * 272 + lmc16;
    const uint32_t v_lm0 = sb + 256 * 272 + lmrow * 144 + lmc16;

    const int vn  = tid & 127;   // d index
    const int vk4 = tid >> 7;    // 0/1

    auto load_q = [&]() {
        for (int i = tid; i < 128 * 16; i += 256) {
            int r = i >> 4;
            int c = (i & 15) * 8;
            cpasync16(sb + r * 272 + c * 2, Qg + (size_t)(q0 + r) * QKV_N + c);
        }
    };
    auto load_k = [&](int j, int buf) {
        const int kb = j * 64;
        const uint32_t kbase = sb + 128 * 272 + buf * 64 * 272;
        for (int i = tid; i < 64 * 16; i += 256) {
            int r = i >> 4;
            int c = (i & 15) * 8;
            cpasync16(kbase + r * 272 + c * 2, Kg + (size_t)(kb + r) * QKV_N + c);
        }
    };

    load_q();
    load_k(0, 0);
    cp_commit();

    float o[16][4];
#pragma unroll
    for (int nt = 0; nt < 16; nt++)
#pragma unroll
        for (int i = 0; i < 4; i++) o[nt][i] = 0.f;
    float m1 = -1e30f, m2 = -1e30f, l1 = 0.f, l2 = 0.f;

    const int njt = 2 * qt + 2;

    // V[0] prefetch into registers (coalesced 2B loads across vn)
    __half vr[32];
#pragma unroll
    for (int t = 0; t < 8; t++) {
        int kv = (vk4 + 2 * t) * 4;
#pragma unroll
        for (int u = 0; u < 4; u++)
            vr[t * 4 + u] = Vg[(size_t)(kv + u) * QKV_N + vn];
    }

    for (int j = 0; j < njt; j++) {
        cp_wait0();                  // K[j] (and Q on j=0) resident

        // store V[j] (transposed) into buffer j&1
        {
            __half* Vb = Vst + (j & 1) * 128 * LDVh;
#pragma unroll
            for (int t = 0; t < 8; t++) {
                int kv = (vk4 + 2 * t) * 4;
                *(__half2*)(Vb + vn * LDVh + kv)     = __halves2half2(vr[t * 4 + 0], vr[t * 4 + 1]);
                *(__half2*)(Vb + vn * LDVh + kv + 2) = __halves2half2(vr[t * 4 + 2], vr[t * 4 + 3]);
            }
        }
        __syncthreads();             // single barrier per iteration

        if (j + 1 < njt) load_k(j + 1, (j + 1) & 1);
        cp_commit();

        // prefetch V[j+1] (hidden under the mma chain below)
        if (j + 1 < njt) {
            const __half* Vt = Vg + (size_t)(j + 1) * 64 * QKV_N;
#pragma unroll
            for (int t = 0; t < 8; t++) {
                int kv = (vk4 + 2 * t) * 4;
#pragma unroll
                for (int u = 0; u < 4; u++)
                    vr[t * 4 + u] = Vt[(size_t)(kv + u) * QKV_N + vn];
            }
        }

        // ---- S = Q @ K^T : warp 16 x 64, d = 128 (8 x k16) ----
        const uint32_t k_lm = k_lm0 + ((j & 1) ? (uint32_t)(64 * 272) : 0u);
        float s[8][4];
#pragma unroll
        for (int nt = 0; nt < 8; nt++)
#pragma unroll
            for (int i = 0; i < 4; i++) s[nt][i] = 0.f;

#pragma unroll
        for (int ks = 0; ks < 8; ks++) {
            uint32_t af[4];
            LDSM4(af[0], af[1], af[2], af[3], q_lm + ks * 32);
            const uint32_t kbb = k_lm + ks * 32;
#pragma unroll
            for (int q = 0; q < 4; q++) {
                uint32_t b0, b1, b2, b3;
                LDSM4(b0, b1, b2, b3, kbb + q * (16 * 272));
                uint32_t bfA[2] = { b0, b2 };
                uint32_t bfB[2] = { b1, b3 };
                mma16(s[2 * q],     af, bfA);
                mma16(s[2 * q + 1], af, bfB);
            }
        }

#pragma unroll
        for (int nt = 0; nt < 8; nt++) {
            s[nt][0] *= scale; s[nt][1] *= scale;
            s[nt][2] *= scale; s[nt][3] *= scale;
        }

        // causal mask (only last two kv tiles clip)
        if (j >= 2 * qt) {
            const int koff = (j - 2 * qt) << 6;
            const int lim1 = r1 - koff;
            const int lim2 = r2 - koff;
#pragma unroll
            for (int nt = 0; nt < 8; nt++) {
                int c0 = nt * 8 + tig * 2;
                if (c0     > lim1) s[nt][0] = -1e30f;
                if (c0 + 1 > lim1) s[nt][1] = -1e30f;
                if (c0     > lim2) s[nt][2] = -1e30f;
                if (c0 + 1 > lim2) s[nt][3] = -1e30f;
            }
        }

        // ---- online softmax (in-warp) ----
        float mx1 = -1e30f, mx2 = -1e30f;
#pragma unroll
        for (int nt = 0; nt < 8; nt++) {
            mx1 = fmaxf(mx1, fmaxf(s[nt][0], s[nt][1]));
            mx2 = fmaxf(mx2, fmaxf(s[nt][2], s[nt][3]));
        }
        mx1 = fmaxf(mx1, __shfl_xor_sync(0xffffffffu, mx1, 1));
        mx1 = fmaxf(mx1, __shfl_xor_sync(0xffffffffu, mx1, 2));
        mx2 = fmaxf(mx2, __shfl_xor_sync(0xffffffffu, mx2, 1));
        mx2 = fmaxf(mx2, __shfl_xor_sync(0xffffffffu, mx2, 2));

        const float mn1 = fmaxf(m1, mx1);
        const float mn2 = fmaxf(m2, mx2);
        const float al1 = __expf(m1 - mn1);
        const float al2 = __expf(m2 - mn2);

        float sm1 = 0.f, sm2 = 0.f;
#pragma unroll
        for (int nt = 0; nt < 8; nt++) {
            s[nt][0] = __expf(s[nt][0] - mn1);
            s[nt][1] = __expf(s[nt][1] - mn1);
            s[nt][2] = __expf(s[nt][2] - mn2);
            s[nt][3] = __expf(s[nt][3] - mn2);
            sm1 += s[nt][0] + s[nt][1];
            sm2 += s[nt][2] + s[nt][3];
        }
        sm1 += __shfl_xor_sync(0xffffffffu, sm1, 1);
        sm1 += __shfl_xor_sync(0xffffffffu, sm1, 2);
        sm2 += __shfl_xor_sync(0xffffffffu, sm2, 1);
        sm2 += __shfl_xor_sync(0xffffffffu, sm2, 2);

        l1 = al1 * l1 + sm1;
        l2 = al2 * l2 + sm2;
        m1 = mn1;
        m2 = mn2;

        // pack P into A-fragment registers (S layout == A layout; no smem!)
        uint32_t ph[8], pl[8];
#pragma unroll
        for (int nt = 0; nt < 8; nt++) {
            ph[nt] = packh2(s[nt][0], s[nt][1]);   // row r1, cols c,c+1
            pl[nt] = packh2(s[nt][2], s[nt][3]);   // row r2
        }

        // rescale O
#pragma unroll
        for (int nt = 0; nt < 16; nt++) {
            o[nt][0] *= al1; o[nt][1] *= al1;
            o[nt][2] *= al2; o[nt][3] *= al2;
        }

        // ---- O += P @ V : warp 16 x 128, kv = 64 (4 x k16) ----
        const uint32_t v_lm = v_lm0 + (j & 1) * (uint32_t)(128 * 144);
#pragma unroll
        for (int ks = 0; ks < 4; ks++) {
            uint32_t af[4] = { ph[2 * ks], pl[2 * ks], ph[2 * ks + 1], pl[2 * ks + 1] };
            const uint32_t vb = v_lm + ks * 32;
#pragma unroll
            for (int q = 0; q < 8; q++) {
                uint32_t b0, b1, b2, b3;
                LDSM4(b0, b1, b2, b3, vb + q * (16 * 144));
                uint32_t bfA[2] = { b0, b2 };
                uint32_t bfB[2] = { b1, b3 };
                mma16(o[2 * q],     af, bfA);
                mma16(o[2 * q + 1], af, bfB);
            }
        }
    }

    const float inv1 = 1.f / l1;
    const float inv2 = 1.f / l2;
    __half* Og = out + ((size_t)b * SEQ + q0) * D_MODEL + h * D_HEAD;
#pragma unroll
    for (int nt = 0; nt < 16; nt++) {
        int c = nt * 8 + tig * 2;
        *(__half2*)(Og + (size_t)r1 * D_MODEL + c) =
            __floats2half2_rn(o[nt][0] * inv1, o[nt][1] * inv1);
        *(__half2*)(Og + (size_t)r2 * D_MODEL + c) =
            __floats2half2_rn(o[nt][2] * inv2, o[nt][3] * inv2);
    }
}

// ============================================================================
// Launch
// ============================================================================
extern "C" void kernel_launch(void* const* d_in, const int* in_sizes, int n_in,
                              void* d_out, int out_size) {
    const float* x    = (const float*)d_in[0];
    const float* Wqkv = (const float*)d_in[1];
    const float* bqkv = (const float*)d_in[2];
    const float* Wout = (const float*)d_in[3];
    const float* bout = (const float*)d_in[4];
    float* out = (float*)d_out;

    __half *qkv_p, *att_p, *xh_p, *wqkvT_p, *woutT_p;
    cudaGetSymbolAddress((void**)&qkv_p, g_qkv);
    cudaGetSymbolAddress((void**)&att_p, g_att);
    cudaGetSymbolAddress((void**)&xh_p, g_xh);
    cudaGetSymbolAddress((void**)&wqkvT_p, g_wqkvT);
    cudaGetSymbolAddress((void**)&woutT_p, g_woutT);

    cudaFuncSetAttribute(gemm_h, cudaFuncAttributeMaxDynamicSharedMemorySize,
                         (int)G_SMEM_BYTES);
    cudaFuncSetAttribute(attn_kernel, cudaFuncAttributeMaxDynamicSharedMemorySize,
                         (int)ATTN_SMEM_BYTES);

    // Prep: fp32 -> fp16 (x), transpose+convert (weights)
    {
        int n4 = BS * D_MODEL / 4;
        conv_half<<<(n4 + 255) / 256, 256>>>(x, xh_p, n4);
        transpose_half<<<dim3(QKV_N / 32, D_MODEL / 32), dim3(32, 8)>>>(Wqkv, wqkvT_p, D_MODEL, QKV_N);
        transpose_half<<<dim3(D_MODEL / 32, D_MODEL / 32), dim3(32, 8)>>>(Wout, woutT_p, D_MODEL, D_MODEL);
    }

    // 1) qkv = x @ W_qkv + b_qkv  [4096, 6144], fp16 out
    gemm_h<<<dim3(QKV_N / 128, BS / 128), 256, G_SMEM_BYTES>>>(
        xh_p, wqkvT_p, bqkv, nullptr, qkv_p, BS, QKV_N, D_MODEL, 1);

    // 2) causal flash attention -> g_att (fp16)
    attn_kernel<<<dim3(SEQ / 128, N_HEADS, BATCH), 256, ATTN_SMEM_BYTES>>>(qkv_p, att_p);

    // 3) out = att @ W_out + b_out  [4096, 2048], fp32 out
    gemm_h<<<dim3(D_MODEL / 128, BS / 128), 256, G_SMEM_BYTES>>>(
        att_p, woutT_p, bout, out, nullptr, BS, D_MODEL, D_MODEL, 0);
}

// round 10
// speedup vs baseline: 1.0635x; 1.0635x over previous
#include <cuda_runtime.h>
#include <cuda_fp16.h>
#include <cstdint>

#define D_MODEL 2048
#define N_HEADS 16
#define D_HEAD  128
#define SEQ     2048
#define BATCH   2
#define BS      (BATCH * SEQ)      // 4096
#define QKV_N   (3 * D_MODEL)      // 6144

// Scratch (allocation-free rule: __device__ globals) — fp16
__device__ __half g_qkv[(size_t)BS * QKV_N];          // 48 MB
__device__ __half g_att[(size_t)BS * D_MODEL];        // 16 MB
__device__ __half g_xh[(size_t)BS * D_MODEL];         // 16 MB
__device__ __half g_wqkvT[(size_t)QKV_N * D_MODEL];   // 24 MB
__device__ __half g_woutT[(size_t)D_MODEL * D_MODEL]; // 8 MB

__device__ __forceinline__ uint32_t smem_u32(const void* p) {
    uint32_t a;
    asm("{ .reg .u64 t; cvta.to.shared.u64 t, %1; cvt.u32.u64 %0, t; }" : "=r"(a) : "l"(p));
    return a;
}

// fp16 mma, fp32 accumulate: D(16x8) += A(16x16) x B(16x8)
__device__ __forceinline__ void mma16(float d[4], const uint32_t a[4], const uint32_t b[2]) {
    asm volatile(
        "mma.sync.aligned.m16n8k16.row.col.f32.f16.f16.f32 "
        "{%0,%1,%2,%3}, {%4,%5,%6,%7}, {%8,%9}, {%0,%1,%2,%3};\n"
        : "+f"(d[0]), "+f"(d[1]), "+f"(d[2]), "+f"(d[3])
        : "r"(a[0]), "r"(a[1]), "r"(a[2]), "r"(a[3]), "r"(b[0]), "r"(b[1]));
}

#define LDSM4(R0, R1, R2, R3, ADDR) \
    asm volatile("ldmatrix.sync.aligned.m8n8.x4.shared.b16 {%0,%1,%2,%3}, [%4];" \
                 : "=r"(R0), "=r"(R1), "=r"(R2), "=r"(R3) : "r"(ADDR))

__device__ __forceinline__ void cpasync16(uint32_t dst, const void* src) {
    asm volatile("cp.async.cg.shared.global [%0], [%1], 16;" :: "r"(dst), "l"(src) : "memory");
}
__device__ __forceinline__ void cp_commit() {
    asm volatile("cp.async.commit_group;" ::: "memory");
}
__device__ __forceinline__ void cp_wait0() {
    asm volatile("cp.async.wait_group 0;" ::: "memory");
}
__device__ __forceinline__ void cp_wait1() {
    asm volatile("cp.async.wait_group 1;" ::: "memory");
}

__device__ __forceinline__ uint32_t packh2(float a, float b) {
    __half2 h = __floats2half2_rn(a, b);
    return *(uint32_t*)&h;
}

// ============================================================================
// Prep kernels: fp32 -> fp16 convert, and transpose-convert for weights.
// ============================================================================
__global__ void conv_half(const float* __restrict__ in, __half* __restrict__ out, int n4) {
    int i = blockIdx.x * blockDim.x + threadIdx.x;
    if (i < n4) {
        float4 v = ((const float4*)in)[i];
        __half2* o = (__half2*)(out) + i * 2;
        o[0] = __floats2half2_rn(v.x, v.y);
        o[1] = __floats2half2_rn(v.z, v.w);
    }
}

// W [K][N] fp32 -> Wt [N][K] fp16
__global__ void transpose_half(const float* __restrict__ W, __half* __restrict__ Wt,
                               int K, int N) {
    __shared__ float t[32][33];
    int n0 = blockIdx.x * 32, k0 = blockIdx.y * 32;
    int tx = threadIdx.x, ty = threadIdx.y;
#pragma unroll
    for (int i = ty; i < 32; i += 8)
        t[i][tx] = W[(size_t)(k0 + i) * N + n0 + tx];
    __syncthreads();
#pragma unroll
    for (int i = ty; i < 32; i += 8)
        Wt[(size_t)(n0 + i) * K + k0 + tx] = __float2half(t[tx][i]);
}

// ============================================================================
// fp16 GEMM (unchanged — at legacy-mma f32-accum ceiling):
// C[M,N] = A[M,K] @ Bt[N,K]^T + bias[N]
// Block 128x128, 8 warps (4x2), warp tile 32x64, K-slab 64 halfs, 3-stage ring.
// ============================================================================
#define G_LDS 72
#define G_TILE_BYTES (128 * G_LDS * 2)              // 18432 per operand
#define G_STAGE_BYTES (2u * G_TILE_BYTES)           // 36864
#define G_SMEM_BYTES (3u * G_STAGE_BYTES)           // 110592

__global__ __launch_bounds__(256, 2) void gemm_h(
    const __half* __restrict__ A, const __half* __restrict__ Bt,
    const float* __restrict__ bias, float* __restrict__ Cf, __half* __restrict__ Ch,
    int M, int N, int K, int store_half)
{
    extern __shared__ __half smem[];
    const uint32_t sbase = smem_u32(smem);

    const int tid  = threadIdx.x;
    const int lane = tid & 31;
    const int wid  = tid >> 5;
    const int wm   = wid >> 1;
    const int wn   = wid & 1;
    const int g    = lane >> 2;
    const int tig  = lane & 3;

    const int m0 = blockIdx.y * 128;
    const int n0 = blockIdx.x * 128;
    const __half* Ag = A + (size_t)m0 * K;
    const __half* Bg = Bt + (size_t)n0 * K;
    const int nslab = K >> 6;

    const int crow = tid >> 3;
    const int ccj  = (tid & 7) * 8;

    const int lmrow = lane & 15;
    const uint32_t lmc16 = (lane >> 4) * 16;
    const uint32_t a_lm = sbase + (wm * 32 + lmrow) * 144 + lmc16;
    const uint32_t b_lm = sbase + (uint32_t)G_TILE_BYTES + (wn * 64 + lmrow) * 144 + lmc16;

    float acc[2][8][4];
#pragma unroll
    for (int mt = 0; mt < 2; mt++)
#pragma unroll
        for (int nt = 0; nt < 8; nt++)
#pragma unroll
            for (int i = 0; i < 4; i++) acc[mt][nt][i] = 0.f;

    auto load_slab = [&](int i, int s) {
        const uint32_t ab = sbase + (uint32_t)s * G_STAGE_BYTES;
        const uint32_t bb = ab + (uint32_t)G_TILE_BYTES;
        const int k0 = i << 6;
#pragma unroll
        for (int r = 0; r < 4; r++) {
            int row = crow + r * 32;
            cpasync16(ab + row * 144 + ccj * 2, Ag + (size_t)row * K + k0 + ccj);
        }
#pragma unroll
        for (int r = 0; r < 4; r++) {
            int row = crow + r * 32;
            cpasync16(bb + row * 144 + ccj * 2, Bg + (size_t)row * K + k0 + ccj);
        }
        cp_commit();
    };

    load_slab(0, 0);
    load_slab(1, 1);

    int s_c = 0;
    int s_l = 2;
    for (int i = 0; i < nslab; i++) {
        cp_wait1();
        __syncthreads();
        if (i + 2 < nslab) load_slab(i + 2, s_l);
        else cp_commit();

        const uint32_t a_st = a_lm + (uint32_t)s_c * G_STAGE_BYTES;
        const uint32_t b_st = b_lm + (uint32_t)s_c * G_STAGE_BYTES;
#pragma unroll
        for (int ks = 0; ks < 4; ks++) {
            const uint32_t ka = a_st + ks * 32;
            uint32_t af0[4], af1[4];
            LDSM4(af0[0], af0[1], af0[2], af0[3], ka);
            LDSM4(af1[0], af1[1], af1[2], af1[3], ka + 2304);
            const uint32_t kb = b_st + ks * 32;
#pragma unroll
            for (int q = 0; q < 4; q++) {
                uint32_t b0, b1, b2, b3;
                LDSM4(b0, b1, b2, b3, kb + q * 2304);
                uint32_t bfA[2] = { b0, b2 };
                uint32_t bfB[2] = { b1, b3 };
                mma16(acc[0][2 * q],     af0, bfA);
                mma16(acc[0][2 * q + 1], af0, bfB);
                mma16(acc[1][2 * q],     af1, bfA);
                mma16(acc[1][2 * q + 1], af1, bfB);
            }
        }
        s_c++; if (s_c == 3) s_c = 0;
        s_l++; if (s_l == 3) s_l = 0;
    }

#pragma unroll
    for (int mt = 0; mt < 2; mt++) {
        int r = m0 + wm * 32 + mt * 16 + g;
#pragma unroll
        for (int nt = 0; nt < 8; nt++) {
            int c = n0 + wn * 64 + nt * 8 + tig * 2;
            float b0 = bias[c], b1 = bias[c + 1];
            float v0 = acc[mt][nt][0] + b0;
            float v1 = acc[mt][nt][1] + b1;
            float v2 = acc[mt][nt][2] + b0;
            float v3 = acc[mt][nt][3] + b1;
            if (store_half) {
                *(__half2*)(Ch + (size_t)r * N + c)       = __floats2half2_rn(v0, v1);
                *(__half2*)(Ch + (size_t)(r + 8) * N + c) = __floats2half2_rn(v2, v3);
            } else {
                *(float2*)(Cf + (size_t)r * N + c)       = make_float2(v0, v1);
                *(float2*)(Cf + (size_t)(r + 8) * N + c) = make_float2(v2, v3);
            }
        }
    }
}

// ============================================================================
// Flash attention (causal), fp16 mma.
// R10: same as R9 (P in registers, double-buffered Vst, one __syncthreads per
// kv-tile, LPT) but WITHOUT the 2-CTA register cap — full reg budget, no spills.
// ============================================================================
#define LDQh 136   // Q/K row stride in halfs (272 B)
#define LDVh 72    // Vst row stride in halfs (144 B)
// Q 128*136 + K 2*64*136 + V 2*128*72 halfs = 53248 halfs = 106496 B
#define ATTN_SMEM_BYTES ((128 * LDQh + 128 * LDQh + 256 * LDVh) * 2)

__global__ __launch_bounds__(256) void attn_kernel(
    const __half* __restrict__ qkv, __half* __restrict__ out)
{
    extern __shared__ __half smh[];
    __half* Vst = smh + 256 * LDQh;         // 2 x [128][72] (row=d, col=kv)

    const int tid  = threadIdx.x;
    const int lane = tid & 31;
    const int wid  = tid >> 5;
    const int g    = lane >> 2;
    const int tig  = lane & 3;
    const int rbase = wid * 16;
    const int r1 = rbase + g;
    const int r2 = r1 + 8;

    const int qt = (int)gridDim.x - 1 - (int)blockIdx.x;   // LPT: largest first
    const int h  = blockIdx.y;
    const int b  = blockIdx.z;
    const int q0 = qt * 128;

    const float scale = 0.08838834764831845f; // 1/sqrt(128)
    const __half* Qg = qkv + (size_t)b * SEQ * QKV_N + h * D_HEAD;
    const __half* Kg = Qg + D_MODEL;
    const __half* Vg = Qg + 2 * D_MODEL;

    const int lmrow = lane & 15;
    const uint32_t lmc16 = (lane >> 4) * 16;
    const uint32_t sb = smem_u32(smh);
    const uint32_t q_lm  = sb + (rbase + lmrow) * 272 + lmc16;
    const uint32_t k_lm0 = sb + 128 * 272 + lmrow * 272 + lmc16;
    const uint32_t v_lm0 = sb + 256 * 272 + lmrow * 144 + lmc16;

    const int vn  = tid & 127;   // d index
    const int vk4 = tid >> 7;    // 0/1

    auto load_q = [&]() {
        for (int i = tid; i < 128 * 16; i += 256) {
            int r = i >> 4;
            int c = (i & 15) * 8;
            cpasync16(sb + r * 272 + c * 2, Qg + (size_t)(q0 + r) * QKV_N + c);
        }
    };
    auto load_k = [&](int j, int buf) {
        const int kb = j * 64;
        const uint32_t kbase = sb + 128 * 272 + buf * 64 * 272;
        for (int i = tid; i < 64 * 16; i += 256) {
            int r = i >> 4;
            int c = (i & 15) * 8;
            cpasync16(kbase + r * 272 + c * 2, Kg + (size_t)(kb + r) * QKV_N + c);
        }
    };

    load_q();
    load_k(0, 0);
    cp_commit();

    float o[16][4];
#pragma unroll
    for (int nt = 0; nt < 16; nt++)
#pragma unroll
        for (int i = 0; i < 4; i++) o[nt][i] = 0.f;
    float m1 = -1e30f, m2 = -1e30f, l1 = 0.f, l2 = 0.f;

    const int njt = 2 * qt + 2;

    // V[0] prefetch into registers (coalesced 2B loads across vn)
    __half vr[32];
#pragma unroll
    for (int t = 0; t < 8; t++) {
        int kv = (vk4 + 2 * t) * 4;
#pragma unroll
        for (int u = 0; u < 4; u++)
            vr[t * 4 + u] = Vg[(size_t)(kv + u) * QKV_N + vn];
    }

    for (int j = 0; j < njt; j++) {
        cp_wait0();                  // K[j] (and Q on j=0) resident

        // store V[j] (transposed) into buffer j&1
        {
            __half* Vb = Vst + (j & 1) * 128 * LDVh;
#pragma unroll
            for (int t = 0; t < 8; t++) {
                int kv = (vk4 + 2 * t) * 4;
                *(__half2*)(Vb + vn * LDVh + kv)     = __halves2half2(vr[t * 4 + 0], vr[t * 4 + 1]);
                *(__half2*)(Vb + vn * LDVh + kv + 2) = __halves2half2(vr[t * 4 + 2], vr[t * 4 + 3]);
            }
        }
        __syncthreads();             // single barrier per iteration

        if (j + 1 < njt) load_k(j + 1, (j + 1) & 1);
        cp_commit();

        // prefetch V[j+1] (hidden under the mma chain below)
        if (j + 1 < njt) {
            const __half* Vt = Vg + (size_t)(j + 1) * 64 * QKV_N;
#pragma unroll
            for (int t = 0; t < 8; t++) {
                int kv = (vk4 + 2 * t) * 4;
#pragma unroll
                for (int u = 0; u < 4; u++)
                    vr[t * 4 + u] = Vt[(size_t)(kv + u) * QKV_N + vn];
            }
        }

        // ---- S = Q @ K^T : warp 16 x 64, d = 128 (8 x k16) ----
        const uint32_t k_lm = k_lm0 + ((j & 1) ? (uint32_t)(64 * 272) : 0u);
        float s[8][4];
#pragma unroll
        for (int nt = 0; nt < 8; nt++)
#pragma unroll
            for (int i = 0; i < 4; i++) s[nt][i] = 0.f;

#pragma unroll
        for (int ks = 0; ks < 8; ks++) {
            uint32_t af[4];
            LDSM4(af[0], af[1], af[2], af[3], q_lm + ks * 32);
            const uint32_t kbb = k_lm + ks * 32;
#pragma unroll
            for (int q = 0; q < 4; q++) {
                uint32_t b0, b1, b2, b3;
                LDSM4(b0, b1, b2, b3, kbb + q * (16 * 272));
                uint32_t bfA[2] = { b0, b2 };
                uint32_t bfB[2] = { b1, b3 };
                mma16(s[2 * q],     af, bfA);
                mma16(s[2 * q + 1], af, bfB);
            }
        }

#pragma unroll
        for (int nt = 0; nt < 8; nt++) {
            s[nt][0] *= scale; s[nt][1] *= scale;
            s[nt][2] *= scale; s[nt][3] *= scale;
        }

        // causal mask (only last two kv tiles clip)
        if (j >= 2 * qt) {
            const int koff = (j - 2 * qt) << 6;
            const int lim1 = r1 - koff;
            const int lim2 = r2 - koff;
#pragma unroll
            for (int nt = 0; nt < 8; nt++) {
                int c0 = nt * 8 + tig * 2;
                if (c0     > lim1) s[nt][0] = -1e30f;
                if (c0 + 1 > lim1) s[nt][1] = -1e30f;
                if (c0     > lim2) s[nt][2] = -1e30f;
                if (c0 + 1 > lim2) s[nt][3] = -1e30f;
            }
        }

        // ---- online softmax (in-warp) ----
        float mx1 = -1e30f, mx2 = -1e30f;
#pragma unroll
        for (int nt = 0; nt < 8; nt++) {
            mx1 = fmaxf(mx1, fmaxf(s[nt][0], s[nt][1]));
            mx2 = fmaxf(mx2, fmaxf(s[nt][2], s[nt][3]));
        }
        mx1 = fmaxf(mx1, __shfl_xor_sync(0xffffffffu, mx1, 1));
        mx1 = fmaxf(mx1, __shfl_xor_sync(0xffffffffu, mx1, 2));
        mx2 = fmaxf(mx2, __shfl_xor_sync(0xffffffffu, mx2, 1));
        mx2 = fmaxf(mx2, __shfl_xor_sync(0xffffffffu, mx2, 2));

        const float mn1 = fmaxf(m1, mx1);
        const float mn2 = fmaxf(m2, mx2);
        const float al1 = __expf(m1 - mn1);
        const float al2 = __expf(m2 - mn2);

        float sm1 = 0.f, sm2 = 0.f;
#pragma unroll
        for (int nt = 0; nt < 8; nt++) {
            s[nt][0] = __expf(s[nt][0] - mn1);
            s[nt][1] = __expf(s[nt][1] - mn1);
            s[nt][2] = __expf(s[nt][2] - mn2);
            s[nt][3] = __expf(s[nt][3] - mn2);
            sm1 += s[nt][0] + s[nt][1];
            sm2 += s[nt][2] + s[nt][3];
        }
        sm1 += __shfl_xor_sync(0xffffffffu, sm1, 1);
        sm1 += __shfl_xor_sync(0xffffffffu, sm1, 2);
        sm2 += __shfl_xor_sync(0xffffffffu, sm2, 1);
        sm2 += __shfl_xor_sync(0xffffffffu, sm2, 2);

        l1 = al1 * l1 + sm1;
        l2 = al2 * l2 + sm2;
        m1 = mn1;
        m2 = mn2;

        // pack P into A-fragment registers (S layout == A layout; no smem)
        uint32_t ph[8], pl[8];
#pragma unroll
        for (int nt = 0; nt < 8; nt++) {
            ph[nt] = packh2(s[nt][0], s[nt][1]);   // row r1, cols c,c+1
            pl[nt] = packh2(s[nt][2], s[nt][3]);   // row r2
        }

        // rescale O
#pragma unroll
        for (int nt = 0; nt < 16; nt++) {
            o[nt][0] *= al1; o[nt][1] *= al1;
            o[nt][2] *= al2; o[nt][3] *= al2;
        }

        // ---- O += P @ V : warp 16 x 128, kv = 64 (4 x k16) ----
        const uint32_t v_lm = v_lm0 + (j & 1) * (uint32_t)(128 * 144);
#pragma unroll
        for (int ks = 0; ks < 4; ks++) {
            uint32_t af[4] = { ph[2 * ks], pl[2 * ks], ph[2 * ks + 1], pl[2 * ks + 1] };
            const uint32_t vb = v_lm + ks * 32;
#pragma unroll
            for (int q = 0; q < 8; q++) {
                uint32_t b0, b1, b2, b3;
                LDSM4(b0, b1, b2, b3, vb + q * (16 * 144));
                uint32_t bfA[2] = { b0, b2 };
                uint32_t bfB[2] = { b1, b3 };
                mma16(o[2 * q],     af, bfA);
                mma16(o[2 * q + 1], af, bfB);
            }
        }
    }

    const float inv1 = 1.f / l1;
    const float inv2 = 1.f / l2;
    __half* Og = out + ((size_t)b * SEQ + q0) * D_MODEL + h * D_HEAD;
#pragma unroll
    for (int nt = 0; nt < 16; nt++) {
        int c = nt * 8 + tig * 2;
        *(__half2*)(Og + (size_t)r1 * D_MODEL + c) =
            __floats2half2_rn(o[nt][0] * inv1, o[nt][1] * inv1);
        *(__half2*)(Og + (size_t)r2 * D_MODEL + c) =
            __floats2half2_rn(o[nt][2] * inv2, o[nt][3] * inv2);
    }
}

// ============================================================================
// Launch
// ============================================================================
extern "C" void kernel_launch(void* const* d_in, const int* in_sizes, int n_in,
                              void* d_out, int out_size) {
    const float* x    = (const float*)d_in[0];
    const float* Wqkv = (const float*)d_in[1];
    const float* bqkv = (const float*)d_in[2];
    const float* Wout = (const float*)d_in[3];
    const float* bout = (const float*)d_in[4];
    float* out = (float*)d_out;

    __half *qkv_p, *att_p, *xh_p, *wqkvT_p, *woutT_p;
    cudaGetSymbolAddress((void**)&qkv_p, g_qkv);
    cudaGetSymbolAddress((void**)&att_p, g_att);
    cudaGetSymbolAddress((void**)&xh_p, g_xh);
    cudaGetSymbolAddress((void**)&wqkvT_p, g_wqkvT);
    cudaGetSymbolAddress((void**)&woutT_p, g_woutT);

    cudaFuncSetAttribute(gemm_h, cudaFuncAttributeMaxDynamicSharedMemorySize,
                         (int)G_SMEM_BYTES);
    cudaFuncSetAttribute(attn_kernel, cudaFuncAttributeMaxDynamicSharedMemorySize,
                         (int)ATTN_SMEM_BYTES);

    // Prep: fp32 -> fp16 (x), transpose+convert (weights)
    {
        int n4 = BS * D_MODEL / 4;
        conv_half<<<(n4 + 255) / 256, 256>>>(x, xh_p, n4);
        transpose_half<<<dim3(QKV_N / 32, D_MODEL / 32), dim3(32, 8)>>>(Wqkv, wqkvT_p, D_MODEL, QKV_N);
        transpose_half<<<dim3(D_MODEL / 32, D_MODEL / 32), dim3(32, 8)>>>(Wout, woutT_p, D_MODEL, D_MODEL);
    }

    // 1) qkv = x @ W_qkv + b_qkv  [4096, 6144], fp16 out
    gemm_h<<<dim3(QKV_N / 128, BS / 128), 256, G_SMEM_BYTES>>>(
        xh_p, wqkvT_p, bqkv, nullptr, qkv_p, BS, QKV_N, D_MODEL, 1);

    // 2) causal flash attention -> g_att (fp16)
    attn_kernel<<<dim3(SEQ / 128, N_HEADS, BATCH), 256, ATTN_SMEM_BYTES>>>(qkv_p, att_p);

    // 3) out = att @ W_out + b_out  [4096, 2048], fp32 out
    gemm_h<<<dim3(D_MODEL / 128, BS / 128), 256, G_SMEM_BYTES>>>(
        att_p, woutT_p, bout, out, nullptr, BS, D_MODEL, D_MODEL, 0);
}

// round 15
// speedup vs baseline: 1.0846x; 1.0198x over previous
#include <cuda_runtime.h>
#include <cuda_fp16.h>
#include <cstdint>

#define D_MODEL 2048
#define N_HEADS 16
#define D_HEAD  128
#define SEQ     2048
#define BATCH   2
#define BS      (BATCH * SEQ)      // 4096
#define QKV_N   (3 * D_MODEL)      // 6144

// Scratch (allocation-free rule: __device__ globals) — fp16
__device__ __half g_qkv[(size_t)BS * QKV_N];          // 48 MB
__device__ __half g_att[(size_t)BS * D_MODEL];        // 16 MB
__device__ __half g_xh[(size_t)BS * D_MODEL];         // 16 MB
__device__ __half g_wqkvT[(size_t)QKV_N * D_MODEL];   // 24 MB
__device__ __half g_woutT[(size_t)D_MODEL * D_MODEL]; // 8 MB

__device__ __forceinline__ uint32_t smem_u32(const void* p) {
    uint32_t a;
    asm("{ .reg .u64 t; cvta.to.shared.u64 t, %1; cvt.u32.u64 %0, t; }" : "=r"(a) : "l"(p));
    return a;
}

// fp16 mma, fp32 accumulate: D(16x8) += A(16x16) x B(16x8)
__device__ __forceinline__ void mma16(float d[4], const uint32_t a[4], const uint32_t b[2]) {
    asm volatile(
        "mma.sync.aligned.m16n8k16.row.col.f32.f16.f16.f32 "
        "{%0,%1,%2,%3}, {%4,%5,%6,%7}, {%8,%9}, {%0,%1,%2,%3};\n"
        : "+f"(d[0]), "+f"(d[1]), "+f"(d[2]), "+f"(d[3])
        : "r"(a[0]), "r"(a[1]), "r"(a[2]), "r"(a[3]), "r"(b[0]), "r"(b[1]));
}

#define LDSM4(R0, R1, R2, R3, ADDR) \
    asm volatile("ldmatrix.sync.aligned.m8n8.x4.shared.b16 {%0,%1,%2,%3}, [%4];" \
                 : "=r"(R0), "=r"(R1), "=r"(R2), "=r"(R3) : "r"(ADDR))

__device__ __forceinline__ void cpasync16(uint32_t dst, const void* src) {
    asm volatile("cp.async.cg.shared.global [%0], [%1], 16;" :: "r"(dst), "l"(src) : "memory");
}
__device__ __forceinline__ void cp_commit() {
    asm volatile("cp.async.commit_group;" ::: "memory");
}
__device__ __forceinline__ void cp_wait0() {
    asm volatile("cp.async.wait_group 0;" ::: "memory");
}
__device__ __forceinline__ void cp_wait1() {
    asm volatile("cp.async.wait_group 1;" ::: "memory");
}

__device__ __forceinline__ uint32_t packh2(float a, float b) {
    __half2 h = __floats2half2_rn(a, b);
    return *(uint32_t*)&h;
}

// ============================================================================
// Prep kernels: fp32 -> fp16 convert, and transpose-convert for weights.
// ============================================================================
__global__ void conv_half(const float* __restrict__ in, __half* __restrict__ out, int n4) {
    int i = blockIdx.x * blockDim.x + threadIdx.x;
    if (i < n4) {
        float4 v = ((const float4*)in)[i];
        __half2* o = (__half2*)(out) + i * 2;
        o[0] = __floats2half2_rn(v.x, v.y);
        o[1] = __floats2half2_rn(v.z, v.w);
    }
}

// W [K][N] fp32 -> Wt [N][K] fp16
__global__ void transpose_half(const float* __restrict__ W, __half* __restrict__ Wt,
                               int K, int N) {
    __shared__ float t[32][33];
    int n0 = blockIdx.x * 32, k0 = blockIdx.y * 32;
    int tx = threadIdx.x, ty = threadIdx.y;
#pragma unroll
    for (int i = ty; i < 32; i += 8)
        t[i][tx] = W[(size_t)(k0 + i) * N + n0 + tx];
    __syncthreads();
#pragma unroll
    for (int i = ty; i < 32; i += 8)
        Wt[(size_t)(n0 + i) * K + k0 + tx] = __float2half(t[tx][i]);
}

// ============================================================================
// fp16 GEMM (at the legacy HMMA f32-acc half-rate ceiling):
// C[M,N] = A[M,K] @ Bt[N,K]^T + bias[N]
// Block 128x128, 8 warps (4x2), warp tile 32x64, K-slab 64 halfs, 3-stage ring.
// store_half: C as fp16 (Ch), with Q columns (n < D_MODEL) pre-scaled by 1/sqrt(d).
// ============================================================================
#define G_LDS 72
#define G_TILE_BYTES (128 * G_LDS * 2)              // 18432 per operand
#define G_STAGE_BYTES (2u * G_TILE_BYTES)           // 36864
#define G_SMEM_BYTES (3u * G_STAGE_BYTES)           // 110592

__global__ __launch_bounds__(256, 2) void gemm_h(
    const __half* __restrict__ A, const __half* __restrict__ Bt,
    const float* __restrict__ bias, float* __restrict__ Cf, __half* __restrict__ Ch,
    int M, int N, int K, int store_half)
{
    extern __shared__ __half smem[];
    const uint32_t sbase = smem_u32(smem);

    const int tid  = threadIdx.x;
    const int lane = tid & 31;
    const int wid  = tid >> 5;
    const int wm   = wid >> 1;
    const int wn   = wid & 1;
    const int g    = lane >> 2;
    const int tig  = lane & 3;

    const int m0 = blockIdx.y * 128;
    const int n0 = blockIdx.x * 128;
    const __half* Ag = A + (size_t)m0 * K;
    const __half* Bg = Bt + (size_t)n0 * K;
    const int nslab = K >> 6;

    const int crow = tid >> 3;
    const int ccj  = (tid & 7) * 8;

    const int lmrow = lane & 15;
    const uint32_t lmc16 = (lane >> 4) * 16;
    const uint32_t a_lm = sbase + (wm * 32 + lmrow) * 144 + lmc16;
    const uint32_t b_lm = sbase + (uint32_t)G_TILE_BYTES + (wn * 64 + lmrow) * 144 + lmc16;

    float acc[2][8][4];
#pragma unroll
    for (int mt = 0; mt < 2; mt++)
#pragma unroll
        for (int nt = 0; nt < 8; nt++)
#pragma unroll
            for (int i = 0; i < 4; i++) acc[mt][nt][i] = 0.f;

    auto load_slab = [&](int i, int s) {
        const uint32_t ab = sbase + (uint32_t)s * G_STAGE_BYTES;
        const uint32_t bb = ab + (uint32_t)G_TILE_BYTES;
        const int k0 = i << 6;
#pragma unroll
        for (int r = 0; r < 4; r++) {
            int row = crow + r * 32;
            cpasync16(ab + row * 144 + ccj * 2, Ag + (size_t)row * K + k0 + ccj);
        }
#pragma unroll
        for (int r = 0; r < 4; r++) {
            int row = crow + r * 32;
            cpasync16(bb + row * 144 + ccj * 2, Bg + (size_t)row * K + k0 + ccj);
        }
        cp_commit();
    };

    load_slab(0, 0);
    load_slab(1, 1);

    int s_c = 0;
    int s_l = 2;
    for (int i = 0; i < nslab; i++) {
        cp_wait1();
        __syncthreads();
        if (i + 2 < nslab) load_slab(i + 2, s_l);
        else cp_commit();

        const uint32_t a_st = a_lm + (uint32_t)s_c * G_STAGE_BYTES;
        const uint32_t b_st = b_lm + (uint32_t)s_c * G_STAGE_BYTES;
#pragma unroll
        for (int ks = 0; ks < 4; ks++) {
            const uint32_t ka = a_st + ks * 32;
            uint32_t af0[4], af1[4];
            LDSM4(af0[0], af0[1], af0[2], af0[3], ka);
            LDSM4(af1[0], af1[1], af1[2], af1[3], ka + 2304);
            const uint32_t kb = b_st + ks * 32;
#pragma unroll
            for (int q = 0; q < 4; q++) {
                uint32_t b0, b1, b2, b3;
                LDSM4(b0, b1, b2, b3, kb + q * 2304);
                uint32_t bfA[2] = { b0, b2 };
                uint32_t bfB[2] = { b1, b3 };
                mma16(acc[0][2 * q],     af0, bfA);
                mma16(acc[0][2 * q + 1], af0, bfB);
                mma16(acc[1][2 * q],     af1, bfA);
                mma16(acc[1][2 * q + 1], af1, bfB);
            }
        }
        s_c++; if (s_c == 3) s_c = 0;
        s_l++; if (s_l == 3) s_l = 0;
    }

    // Fold attention's 1/sqrt(d) into the Q block of qkv (whole CTA tile is
    // either inside or outside the Q columns since n0 is a multiple of 128).
    const float cscale = (store_half && n0 < D_MODEL) ? 0.08838834764831845f : 1.0f;

#pragma unroll
    for (int mt = 0; mt < 2; mt++) {
        int r = m0 + wm * 32 + mt * 16 + g;
#pragma unroll
        for (int nt = 0; nt < 8; nt++) {
            int c = n0 + wn * 64 + nt * 8 + tig * 2;
            float b0 = bias[c], b1 = bias[c + 1];
            float v0 = (acc[mt][nt][0] + b0) * cscale;
            float v1 = (acc[mt][nt][1] + b1) * cscale;
            float v2 = (acc[mt][nt][2] + b0) * cscale;
            float v3 = (acc[mt][nt][3] + b1) * cscale;
            if (store_half) {
                *(__half2*)(Ch + (size_t)r * N + c)       = __floats2half2_rn(v0, v1);
                *(__half2*)(Ch + (size_t)(r + 8) * N + c) = __floats2half2_rn(v2, v3);
            } else {
                *(float2*)(Cf + (size_t)r * N + c)       = make_float2(v0, v1);
                *(float2*)(Cf + (size_t)(r + 8) * N + c) = make_float2(v2, v3);
            }
        }
    }
}

// ============================================================================
// Flash attention (causal), fp16 mma.
// Q fragments hoisted out of the kv loop (loaded once at j=0);
// fully-masked warps skip the last diagonal tile; scale pre-folded into Q.
// P in registers, double-buffered Vst, one __syncthreads per kv-tile, LPT.
// ============================================================================
#define LDQh 136   // Q/K row stride in halfs (272 B)
#define LDVh 72    // Vst row stride in halfs (144 B)
// Q 128*136 + K 2*64*136 + V 2*128*72 halfs = 53248 halfs = 106496 B
#define ATTN_SMEM_BYTES ((128 * LDQh + 128 * LDQh + 256 * LDVh) * 2)

__global__ __launch_bounds__(256) void attn_kernel(
    const __half* __restrict__ qkv, __half* __restrict__ out)
{
    extern __shared__ __half smh[];
    __half* Vst = smh + 256 * LDQh;         // 2 x [128][72] (row=d, col=kv)

    const int tid  = threadIdx.x;
    const int lane = tid & 31;
    const int wid  = tid >> 5;
    const int g    = lane >> 2;
    const int tig  = lane & 3;
    const int rbase = wid * 16;
    const int r1 = rbase + g;
    const int r2 = r1 + 8;

    const int qt = (int)gridDim.x - 1 - (int)blockIdx.x;   // LPT: largest first
    const int h  = blockIdx.y;
    const int b  = blockIdx.z;
    const int q0 = qt * 128;

    const __half* Qg = qkv + (size_t)b * SEQ * QKV_N + h * D_HEAD;   // pre-scaled
    const __half* Kg = Qg + D_MODEL;
    const __half* Vg = Qg + 2 * D_MODEL;

    const int lmrow = lane & 15;
    const uint32_t lmc16 = (lane >> 4) * 16;
    const uint32_t sb = smem_u32(smh);
    const uint32_t q_lm  = sb + (rbase + lmrow) * 272 + lmc16;
    const uint32_t k_lm0 = sb + 128 * 272 + lmrow * 272 + lmc16;
    const uint32_t v_lm0 = sb + 256 * 272 + lmrow * 144 + lmc16;

    const int vn  = tid & 127;   // d index
    const int vk4 = tid >> 7;    // 0/1

    auto load_q = [&]() {
        for (int i = tid; i < 128 * 16; i += 256) {
            int r = i >> 4;
            int c = (i & 15) * 8;
            cpasync16(sb + r * 272 + c * 2, Qg + (size_t)(q0 + r) * QKV_N + c);
        }
    };
    auto load_k = [&](int j, int buf) {
        const int kb = j * 64;
        const uint32_t kbase = sb + 128 * 272 + buf * 64 * 272;
        for (int i = tid; i < 64 * 16; i += 256) {
            int r = i >> 4;
            int c = (i & 15) * 8;
            cpasync16(kbase + r * 272 + c * 2, Kg + (size_t)(kb + r) * QKV_N + c);
        }
    };

    load_q();
    load_k(0, 0);
    cp_commit();

    float o[16][4];
#pragma unroll
    for (int nt = 0; nt < 16; nt++)
#pragma unroll
        for (int i = 0; i < 4; i++) o[nt][i] = 0.f;
    float m1 = -1e30f, m2 = -1e30f, l1 = 0.f, l2 = 0.f;

    uint32_t qf[8][4];   // Q fragments, loaded once at j=0

    const int njt = 2 * qt + 2;

    // V[0] prefetch into registers (coalesced 2B loads across vn)
    __half vr[32];
#pragma unroll
    for (int t = 0; t < 8; t++) {
        int kv = (vk4 + 2 * t) * 4;
#pragma unroll
        for (int u = 0; u < 4; u++)
            vr[t * 4 + u] = Vg[(size_t)(kv + u) * QKV_N + vn];
    }

    for (int j = 0; j < njt; j++) {
        cp_wait0();                  // K[j] (and Q on j=0) resident

        // store V[j] (transposed) into buffer j&1
        {
            __half* Vb = Vst + (j & 1) * 128 * LDVh;
#pragma unroll
            for (int t = 0; t < 8; t++) {
                int kv = (vk4 + 2 * t) * 4;
                *(__half2*)(Vb + vn * LDVh + kv)     = __halves2half2(vr[t * 4 + 0], vr[t * 4 + 1]);
                *(__half2*)(Vb + vn * LDVh + kv + 2) = __halves2half2(vr[t * 4 + 2], vr[t * 4 + 3]);
            }
        }
        __syncthreads();             // single barrier per iteration

        if (j == 0) {
            // Q resident + visible (every thread passed cp_wait0 before barrier)
#pragma unroll
            for (int ks = 0; ks < 8; ks++)
                LDSM4(qf[ks][0], qf[ks][1], qf[ks][2], qf[ks][3], q_lm + ks * 32);
        }

        if (j + 1 < njt) load_k(j + 1, (j + 1) & 1);
        cp_commit();

        // prefetch V[j+1] (hidden under the mma chain below)
        if (j + 1 < njt) {
            const __half* Vt = Vg + (size_t)(j + 1) * 64 * QKV_N;
#pragma unroll
            for (int t = 0; t < 8; t++) {
                int kv = (vk4 + 2 * t) * 4;
#pragma unroll
                for (int u = 0; u < 4; u++)
                    vr[t * 4 + u] = Vt[(size_t)(kv + u) * QKV_N + vn];
            }
        }

        // Fully-masked warp skip: last diagonal tile (koff=64) gives warps with
        // rows < 64 zero visible keys -> P would be all zero; skip compute.
        if (j == 2 * qt + 1 && rbase < 64) continue;

        // ---- S = Q @ K^T : warp 16 x 64, d = 128 (8 x k16) ----
        const uint32_t k_lm = k_lm0 + ((j & 1) ? (uint32_t)(64 * 272) : 0u);
        float s[8][4];
#pragma unroll
        for (int nt = 0; nt < 8; nt++)
#pragma unroll
            for (int i = 0; i < 4; i++) s[nt][i] = 0.f;

#pragma unroll
        for (int ks = 0; ks < 8; ks++) {
            const uint32_t kbb = k_lm + ks * 32;
#pragma unroll
            for (int q = 0; q < 4; q++) {
                uint32_t b0, b1, b2, b3;
                LDSM4(b0, b1, b2, b3, kbb + q * (16 * 272));
                uint32_t bfA[2] = { b0, b2 };
                uint32_t bfB[2] = { b1, b3 };
                mma16(s[2 * q],     qf[ks], bfA);
                mma16(s[2 * q + 1], qf[ks], bfB);
            }
        }

        // causal mask (only last two kv tiles clip)
        if (j >= 2 * qt) {
            const int koff = (j - 2 * qt) << 6;
            const int lim1 = r1 - koff;
            const int lim2 = r2 - koff;
#pragma unroll
            for (int nt = 0; nt < 8; nt++) {
                int c0 = nt * 8 + tig * 2;
                if (c0     > lim1) s[nt][0] = -1e30f;
                if (c0 + 1 > lim1) s[nt][1] = -1e30f;
                if (c0     > lim2) s[nt][2] = -1e30f;
                if (c0 + 1 > lim2) s[nt][3] = -1e30f;
            }
        }

        // ---- online softmax (in-warp) ----
        float mx1 = -1e30f, mx2 = -1e30f;
#pragma unroll
        for (int nt = 0; nt < 8; nt++) {
            mx1 = fmaxf(mx1, fmaxf(s[nt][0], s[nt][1]));
            mx2 = fmaxf(mx2, fmaxf(s[nt][2], s[nt][3]));
        }
        mx1 = fmaxf(mx1, __shfl_xor_sync(0xffffffffu, mx1, 1));
        mx1 = fmaxf(mx1, __shfl_xor_sync(0xffffffffu, mx1, 2));
        mx2 = fmaxf(mx2, __shfl_xor_sync(0xffffffffu, mx2, 1));
        mx2 = fmaxf(mx2, __shfl_xor_sync(0xffffffffu, mx2, 2));

        const float mn1 = fmaxf(m1, mx1);
        const float mn2 = fmaxf(m2, mx2);
        const float al1 = __expf(m1 - mn1);
        const float al2 = __expf(m2 - mn2);

        float sm1 = 0.f, sm2 = 0.f;
#pragma unroll
        for (int nt = 0; nt < 8; nt++) {
            s[nt][0] = __expf(s[nt][0] - mn1);
            s[nt][1] = __expf(s[nt][1] - mn1);
            s[nt][2] = __expf(s[nt][2] - mn2);
            s[nt][3] = __expf(s[nt][3] - mn2);
            sm1 += s[nt][0] + s[nt][1];
            sm2 += s[nt][2] + s[nt][3];
        }
        sm1 += __shfl_xor_sync(0xffffffffu, sm1, 1);
        sm1 += __shfl_xor_sync(0xffffffffu, sm1, 2);
        sm2 += __shfl_xor_sync(0xffffffffu, sm2, 1);
        sm2 += __shfl_xor_sync(0xffffffffu, sm2, 2);

        l1 = al1 * l1 + sm1;
        l2 = al2 * l2 + sm2;
        m1 = mn1;
        m2 = mn2;

        // pack P into A-fragment registers (S layout == A layout; no smem)
        uint32_t ph[8], pl[8];
#pragma unroll
        for (int nt = 0; nt < 8; nt++) {
            ph[nt] = packh2(s[nt][0], s[nt][1]);   // row r1, cols c,c+1
            pl[nt] = packh2(s[nt][2], s[nt][3]);   // row r2
        }

        // rescale O
#pragma unroll
        for (int nt = 0; nt < 16; nt++) {
            o[nt][0] *= al1; o[nt][1] *= al1;
            o[nt][2] *= al2; o[nt][3] *= al2;
        }

        // ---- O += P @ V : warp 16 x 128, kv = 64 (4 x k16) ----
        const uint32_t v_lm = v_lm0 + (j & 1) * (uint32_t)(128 * 144);
#pragma unroll
        for (int ks = 0; ks < 4; ks++) {
            uint32_t af[4] = { ph[2 * ks], pl[2 * ks], ph[2 * ks + 1], pl[2 * ks + 1] };
            const uint32_t vb = v_lm + ks * 32;
#pragma unroll
            for (int q = 0; q < 8; q++) {
                uint32_t b0, b1, b2, b3;
                LDSM4(b0, b1, b2, b3, vb + q * (16 * 144));
                uint32_t bfA[2] = { b0, b2 };
                uint32_t bfB[2] = { b1, b3 };
                mma16(o[2 * q],     af, bfA);
                mma16(o[2 * q + 1], af, bfB);
            }
        }
    }

    const float inv1 = 1.f / l1;
    const float inv2 = 1.f / l2;
    __half* Og = out + ((size_t)b * SEQ + q0) * D_MODEL + h * D_HEAD;
#pragma unroll
    for (int nt = 0; nt < 16; nt++) {
        int c = nt * 8 + tig * 2;
        *(__half2*)(Og + (size_t)r1 * D_MODEL + c) =
            __floats2half2_rn(o[nt][0] * inv1, o[nt][1] * inv1);
        *(__half2*)(Og + (size_t)r2 * D_MODEL + c) =
            __floats2half2_rn(o[nt][2] * inv2, o[nt][3] * inv2);
    }
}

// ============================================================================
// Launch
// ============================================================================
extern "C" void kernel_launch(void* const* d_in, const int* in_sizes, int n_in,
                              void* d_out, int out_size) {
    const float* x    = (const float*)d_in[0];
    const float* Wqkv = (const float*)d_in[1];
    const float* bqkv = (const float*)d_in[2];
    const float* Wout = (const float*)d_in[3];
    const float* bout = (const float*)d_in[4];
    float* out = (float*)d_out;

    __half *qkv_p, *att_p, *xh_p, *wqkvT_p, *woutT_p;
    cudaGetSymbolAddress((void**)&qkv_p, g_qkv);
    cudaGetSymbolAddress((void**)&att_p, g_att);
    cudaGetSymbolAddress((void**)&xh_p, g_xh);
    cudaGetSymbolAddress((void**)&wqkvT_p, g_wqkvT);
    cudaGetSymbolAddress((void**)&woutT_p, g_woutT);

    cudaFuncSetAttribute(gemm_h, cudaFuncAttributeMaxDynamicSharedMemorySize,
                         (int)G_SMEM_BYTES);
    cudaFuncSetAttribute(attn_kernel, cudaFuncAttributeMaxDynamicSharedMemorySize,
                         (int)ATTN_SMEM_BYTES);

    // Prep: fp32 -> fp16 (x), transpose+convert (weights)
    {
        int n4 = BS * D_MODEL / 4;
        conv_half<<<(n4 + 255) / 256, 256>>>(x, xh_p, n4);
        transpose_half<<<dim3(QKV_N / 32, D_MODEL / 32), dim3(32, 8)>>>(Wqkv, wqkvT_p, D_MODEL, QKV_N);
        transpose_half<<<dim3(D_MODEL / 32, D_MODEL / 32), dim3(32, 8)>>>(Wout, woutT_p, D_MODEL, D_MODEL);
    }

    // 1) qkv = x @ W_qkv + b_qkv  [4096, 6144], fp16 out, Q columns pre-scaled
    gemm_h<<<dim3(QKV_N / 128, BS / 128), 256, G_SMEM_BYTES>>>(
        xh_p, wqkvT_p, bqkv, nullptr, qkv_p, BS, QKV_N, D_MODEL, 1);

    // 2) causal flash attention -> g_att (fp16)
    attn_kernel<<<dim3(SEQ / 128, N_HEADS, BATCH), 256, ATTN_SMEM_BYTES>>>(qkv_p, att_p);

    // 3) out = att @ W_out + b_out  [4096, 2048], fp32 out
    gemm_h<<<dim3(D_MODEL / 128, BS / 128), 256, G_SMEM_BYTES>>>(
        att_p, woutT_p, bout, out, nullptr, BS, D_MODEL, D_MODEL, 0);
}

// round 16
// speedup vs baseline: 1.1696x; 1.0784x over previous
#include <cuda_runtime.h>
#include <cuda_fp16.h>
#include <cstdint>

#define D_MODEL 2048
#define N_HEADS 16
#define D_HEAD  128
#define SEQ     2048
#define BATCH   2
#define BS      (BATCH * SEQ)      // 4096
#define QKV_N   (3 * D_MODEL)      // 6144

// Scratch (allocation-free rule: __device__ globals) — fp16
__device__ __half g_qkv[(size_t)BS * QKV_N];          // 48 MB
__device__ __half g_att[(size_t)BS * D_MODEL];        // 16 MB
__device__ __half g_xh[(size_t)BS * D_MODEL];         // 16 MB
__device__ __half g_wqkvT[(size_t)QKV_N * D_MODEL];   // 24 MB
__device__ __half g_woutT[(size_t)D_MODEL * D_MODEL]; // 8 MB

__device__ __forceinline__ uint32_t smem_u32(const void* p) {
    uint32_t a;
    asm("{ .reg .u64 t; cvta.to.shared.u64 t, %1; cvt.u32.u64 %0, t; }" : "=r"(a) : "l"(p));
    return a;
}

// fp16 mma, fp32 accumulate: D(16x8) += A(16x16) x B(16x8)
__device__ __forceinline__ void mma16(float d[4], const uint32_t a[4], const uint32_t b[2]) {
    asm volatile(
        "mma.sync.aligned.m16n8k16.row.col.f32.f16.f16.f32 "
        "{%0,%1,%2,%3}, {%4,%5,%6,%7}, {%8,%9}, {%0,%1,%2,%3};\n"
        : "+f"(d[0]), "+f"(d[1]), "+f"(d[2]), "+f"(d[3])
        : "r"(a[0]), "r"(a[1]), "r"(a[2]), "r"(a[3]), "r"(b[0]), "r"(b[1]));
}

#define LDSM4(R0, R1, R2, R3, ADDR) \
    asm volatile("ldmatrix.sync.aligned.m8n8.x4.shared.b16 {%0,%1,%2,%3}, [%4];" \
                 : "=r"(R0), "=r"(R1), "=r"(R2), "=r"(R3) : "r"(ADDR))

#define LDSM4T(R0, R1, R2, R3, ADDR) \
    asm volatile("ldmatrix.sync.aligned.m8n8.x4.trans.shared.b16 {%0,%1,%2,%3}, [%4];" \
                 : "=r"(R0), "=r"(R1), "=r"(R2), "=r"(R3) : "r"(ADDR))

__device__ __forceinline__ void cpasync16(uint32_t dst, const void* src) {
    asm volatile("cp.async.cg.shared.global [%0], [%1], 16;" :: "r"(dst), "l"(src) : "memory");
}
__device__ __forceinline__ void cp_commit() {
    asm volatile("cp.async.commit_group;" ::: "memory");
}
__device__ __forceinline__ void cp_wait0() {
    asm volatile("cp.async.wait_group 0;" ::: "memory");
}
__device__ __forceinline__ void cp_wait1() {
    asm volatile("cp.async.wait_group 1;" ::: "memory");
}

__device__ __forceinline__ uint32_t packh2(float a, float b) {
    __half2 h = __floats2half2_rn(a, b);
    return *(uint32_t*)&h;
}

// ============================================================================
// Fused prep kernel: one launch. Block ranges:
//   [0, NB_CONV)                 : x fp32 -> fp16
//   [NB_CONV, +NB_WQKV)          : W_qkv transpose+convert
//   [NB_CONV+NB_WQKV, +NB_WOUT)  : W_out transpose+convert
// ============================================================================
#define NB_CONV (BS * D_MODEL / 4 / 256)               // 4096
#define NB_WQKV ((QKV_N / 32) * (D_MODEL / 32))        // 12288
#define NB_WOUT ((D_MODEL / 32) * (D_MODEL / 32))      // 4096
#define NB_PREP (NB_CONV + NB_WQKV + NB_WOUT)

__global__ __launch_bounds__(256) void prep_all(
    const float* __restrict__ x, __half* __restrict__ xh,
    const float* __restrict__ Wqkv, __half* __restrict__ WqkvT,
    const float* __restrict__ Wout, __half* __restrict__ WoutT)
{
    const int blk = blockIdx.x;
    const int tid = threadIdx.x;

    if (blk < NB_CONV) {
        int i = blk * 256 + tid;
        float4 v = ((const float4*)x)[i];
        __half2* o = (__half2*)(xh) + i * 2;
        o[0] = __floats2half2_rn(v.x, v.y);
        o[1] = __floats2half2_rn(v.z, v.w);
        return;
    }

    __shared__ float t[32][33];
    const int tx = tid & 31;
    const int ty = tid >> 5;    // 0..7

    const float* W;
    __half* Wt;
    int K, N, tb;
    if (blk < NB_CONV + NB_WQKV) {
        W = Wqkv; Wt = WqkvT; K = D_MODEL; N = QKV_N;
        tb = blk - NB_CONV;
    } else {
        W = Wout; Wt = WoutT; K = D_MODEL; N = D_MODEL;
        tb = blk - NB_CONV - NB_WQKV;
    }
    const int ntx = N / 32;
    const int n0 = (tb % ntx) * 32;
    const int k0 = (tb / ntx) * 32;

#pragma unroll
    for (int i = ty; i < 32; i += 8)
        t[i][tx] = W[(size_t)(k0 + i) * N + n0 + tx];
    __syncthreads();
#pragma unroll
    for (int i = ty; i < 32; i += 8)
        Wt[(size_t)(n0 + i) * K + k0 + tx] = __float2half(t[tx][i]);
}

// ============================================================================
// fp16 GEMM (unchanged — at the legacy HMMA f32-acc half-rate ceiling):
// C[M,N] = A[M,K] @ Bt[N,K]^T + bias[N]
// Block 128x128, 8 warps (4x2), warp tile 32x64, K-slab 64 halfs, 3-stage ring.
// store_half: C as fp16 (Ch), with Q columns (n < D_MODEL) pre-scaled by 1/sqrt(d).
// ============================================================================
#define G_LDS 72
#define G_TILE_BYTES (128 * G_LDS * 2)              // 18432 per operand
#define G_STAGE_BYTES (2u * G_TILE_BYTES)           // 36864
#define G_SMEM_BYTES (3u * G_STAGE_BYTES)           // 110592

__global__ __launch_bounds__(256, 2) void gemm_h(
    const __half* __restrict__ A, const __half* __restrict__ Bt,
    const float* __restrict__ bias, float* __restrict__ Cf, __half* __restrict__ Ch,
    int M, int N, int K, int store_half)
{
    extern __shared__ __half smem[];
    const uint32_t sbase = smem_u32(smem);

    const int tid  = threadIdx.x;
    const int lane = tid & 31;
    const int wid  = tid >> 5;
    const int wm   = wid >> 1;
    const int wn   = wid & 1;
    const int g    = lane >> 2;
    const int tig  = lane & 3;

    const int m0 = blockIdx.y * 128;
    const int n0 = blockIdx.x * 128;
    const __half* Ag = A + (size_t)m0 * K;
    const __half* Bg = Bt + (size_t)n0 * K;
    const int nslab = K >> 6;

    const int crow = tid >> 3;
    const int ccj  = (tid & 7) * 8;

    const int lmrow = lane & 15;
    const uint32_t lmc16 = (lane >> 4) * 16;
    const uint32_t a_lm = sbase + (wm * 32 + lmrow) * 144 + lmc16;
    const uint32_t b_lm = sbase + (uint32_t)G_TILE_BYTES + (wn * 64 + lmrow) * 144 + lmc16;

    float acc[2][8][4];
#pragma unroll
    for (int mt = 0; mt < 2; mt++)
#pragma unroll
        for (int nt = 0; nt < 8; nt++)
#pragma unroll
            for (int i = 0; i < 4; i++) acc[mt][nt][i] = 0.f;

    auto load_slab = [&](int i, int s) {
        const uint32_t ab = sbase + (uint32_t)s * G_STAGE_BYTES;
        const uint32_t bb = ab + (uint32_t)G_TILE_BYTES;
        const int k0 = i << 6;
#pragma unroll
        for (int r = 0; r < 4; r++) {
            int row = crow + r * 32;
            cpasync16(ab + row * 144 + ccj * 2, Ag + (size_t)row * K + k0 + ccj);
        }
#pragma unroll
        for (int r = 0; r < 4; r++) {
            int row = crow + r * 32;
            cpasync16(bb + row * 144 + ccj * 2, Bg + (size_t)row * K + k0 + ccj);
        }
        cp_commit();
    };

    load_slab(0, 0);
    load_slab(1, 1);

    int s_c = 0;
    int s_l = 2;
    for (int i = 0; i < nslab; i++) {
        cp_wait1();
        __syncthreads();
        if (i + 2 < nslab) load_slab(i + 2, s_l);
        else cp_commit();

        const uint32_t a_st = a_lm + (uint32_t)s_c * G_STAGE_BYTES;
        const uint32_t b_st = b_lm + (uint32_t)s_c * G_STAGE_BYTES;
#pragma unroll
        for (int ks = 0; ks < 4; ks++) {
            const uint32_t ka = a_st + ks * 32;
            uint32_t af0[4], af1[4];
            LDSM4(af0[0], af0[1], af0[2], af0[3], ka);
            LDSM4(af1[0], af1[1], af1[2], af1[3], ka + 2304);
            const uint32_t kb = b_st + ks * 32;
#pragma unroll
            for (int q = 0; q < 4; q++) {
                uint32_t b0, b1, b2, b3;
                LDSM4(b0, b1, b2, b3, kb + q * 2304);
                uint32_t bfA[2] = { b0, b2 };
                uint32_t bfB[2] = { b1, b3 };
                mma16(acc[0][2 * q],     af0, bfA);
                mma16(acc[0][2 * q + 1], af0, bfB);
                mma16(acc[1][2 * q],     af1, bfA);
                mma16(acc[1][2 * q + 1], af1, bfB);
            }
        }
        s_c++; if (s_c == 3) s_c = 0;
        s_l++; if (s_l == 3) s_l = 0;
    }

    const float cscale = (store_half && n0 < D_MODEL) ? 0.08838834764831845f : 1.0f;

#pragma unroll
    for (int mt = 0; mt < 2; mt++) {
        int r = m0 + wm * 32 + mt * 16 + g;
#pragma unroll
        for (int nt = 0; nt < 8; nt++) {
            int c = n0 + wn * 64 + nt * 8 + tig * 2;
            float b0 = bias[c], b1 = bias[c + 1];
            float v0 = (acc[mt][nt][0] + b0) * cscale;
            float v1 = (acc[mt][nt][1] + b1) * cscale;
            float v2 = (acc[mt][nt][2] + b0) * cscale;
            float v3 = (acc[mt][nt][3] + b1) * cscale;
            if (store_half) {
                *(__half2*)(Ch + (size_t)r * N + c)       = __floats2half2_rn(v0, v1);
                *(__half2*)(Ch + (size_t)(r + 8) * N + c) = __floats2half2_rn(v2, v3);
            } else {
                *(float2*)(Cf + (size_t)r * N + c)       = make_float2(v0, v1);
                *(float2*)(Cf + (size_t)(r + 8) * N + c) = make_float2(v2, v3);
            }
        }
    }
}

// ============================================================================
// Flash attention (causal), fp16 mma.
// R16: V via cp.async (double-buffered, same 272B-stride rows as K) and PV
// B-fragments via ldmatrix.trans — register V gather + transposed STS deleted.
// Q fragments hoisted; masked-warp skip; scale pre-folded into Q; P in regs;
// one __syncthreads per kv-tile; LPT.
// ============================================================================
// Byte layout (all rows 272 B = 136 halfs; stride 68 words ≡ 4 mod 32 ->
// conflict-free for both normal and trans ldmatrix):
//   Q  : [0,            34816)        128 rows
//   K  : [34816,        34816+34816)  2 x 64 rows
//   V  : [69632,        69632+34816)  2 x 64 rows
#define ATTN_SMEM_BYTES (384 * 272)

__global__ __launch_bounds__(256) void attn_kernel(
    const __half* __restrict__ qkv, __half* __restrict__ out)
{
    extern __shared__ __half smh[];

    const int tid  = threadIdx.x;
    const int lane = tid & 31;
    const int wid  = tid >> 5;
    const int g    = lane >> 2;
    const int tig  = lane & 3;
    const int rbase = wid * 16;
    const int r1 = rbase + g;
    const int r2 = r1 + 8;

    const int qt = (int)gridDim.x - 1 - (int)blockIdx.x;   // LPT: largest first
    const int h  = blockIdx.y;
    const int b  = blockIdx.z;
    const int q0 = qt * 128;

    const __half* Qg = qkv + (size_t)b * SEQ * QKV_N + h * D_HEAD;   // pre-scaled
    const __half* Kg = Qg + D_MODEL;
    const __half* Vg = Qg + 2 * D_MODEL;

    const uint32_t sb = smem_u32(smh);
    const uint32_t kb_base = sb + 34816u;
    const uint32_t vb_base = sb + 69632u;

    // ldmatrix lane addressing
    const int lmrow = lane & 15;
    const uint32_t lmc16 = (lane >> 4) * 16;
    const uint32_t q_lm  = sb + (rbase + lmrow) * 272 + lmc16;
    const uint32_t k_lm0 = kb_base + lmrow * 272 + lmc16;
    // trans-V: lanes 0-7 rows 0-7 col d0; 8-15 rows 8-15 col d0;
    //          16-23 rows 0-7 col d0+8; 24-31 rows 8-15 col d0+8
    const uint32_t v_lm0 = vb_base + (((lane >> 3) & 1) * 8 + (lane & 7)) * 272
                                   + (lane >> 4) * 16;

    auto load_q = [&]() {
        for (int i = tid; i < 128 * 16; i += 256) {
            int r = i >> 4;
            int c = (i & 15) * 8;
            cpasync16(sb + r * 272 + c * 2, Qg + (size_t)(q0 + r) * QKV_N + c);
        }
    };
    auto load_k = [&](int j, int buf) {
        const int kb = j * 64;
        const uint32_t kbase = kb_base + buf * (64u * 272u);
        for (int i = tid; i < 64 * 16; i += 256) {
            int r = i >> 4;
            int c = (i & 15) * 8;
            cpasync16(kbase + r * 272 + c * 2, Kg + (size_t)(kb + r) * QKV_N + c);
        }
    };
    auto load_v = [&](int j, int buf) {
        const int kb = j * 64;
        const uint32_t vbase = vb_base + buf * (64u * 272u);
        for (int i = tid; i < 64 * 16; i += 256) {
            int r = i >> 4;
            int c = (i & 15) * 8;
            cpasync16(vbase + r * 272 + c * 2, Vg + (size_t)(kb + r) * QKV_N + c);
        }
    };

    load_q();
    load_k(0, 0);
    load_v(0, 0);
    cp_commit();

    float o[16][4];
#pragma unroll
    for (int nt = 0; nt < 16; nt++)
#pragma unroll
        for (int i = 0; i < 4; i++) o[nt][i] = 0.f;
    float m1 = -1e30f, m2 = -1e30f, l1 = 0.f, l2 = 0.f;

    uint32_t qf[8][4];   // Q fragments, loaded once at j=0

    const int njt = 2 * qt + 2;

    for (int j = 0; j < njt; j++) {
        cp_wait0();                  // K[j], V[j] (and Q on j=0) resident
        __syncthreads();             // all warps done reading buffers j-1

        if (j == 0) {
#pragma unroll
            for (int ks = 0; ks < 8; ks++)
                LDSM4(qf[ks][0], qf[ks][1], qf[ks][2], qf[ks][3], q_lm + ks * 32);
        }

        if (j + 1 < njt) {
            load_k(j + 1, (j + 1) & 1);
            load_v(j + 1, (j + 1) & 1);
        }
        cp_commit();

        // Fully-masked warp skip on the last diagonal tile
        if (j == 2 * qt + 1 && rbase < 64) continue;

        // ---- S = Q @ K^T : warp 16 x 64, d = 128 (8 x k16) ----
        const uint32_t k_lm = k_lm0 + ((j & 1) ? (64u * 272u) : 0u);
        float s[8][4];
#pragma unroll
        for (int nt = 0; nt < 8; nt++)
#pragma unroll
            for (int i = 0; i < 4; i++) s[nt][i] = 0.f;

#pragma unroll
        for (int ks = 0; ks < 8; ks++) {
            const uint32_t kbb = k_lm + ks * 32;
#pragma unroll
            for (int q = 0; q < 4; q++) {
                uint32_t b0, b1, b2, b3;
                LDSM4(b0, b1, b2, b3, kbb + q * (16 * 272));
                uint32_t bfA[2] = { b0, b2 };
                uint32_t bfB[2] = { b1, b3 };
                mma16(s[2 * q],     qf[ks], bfA);
                mma16(s[2 * q + 1], qf[ks], bfB);
            }
        }

        // causal mask (only last two kv tiles clip)
        if (j >= 2 * qt) {
            const int koff = (j - 2 * qt) << 6;
            const int lim1 = r1 - koff;
            const int lim2 = r2 - koff;
#pragma unroll
            for (int nt = 0; nt < 8; nt++) {
                int c0 = nt * 8 + tig * 2;
                if (c0     > lim1) s[nt][0] = -1e30f;
                if (c0 + 1 > lim1) s[nt][1] = -1e30f;
                if (c0     > lim2) s[nt][2] = -1e30f;
                if (c0 + 1 > lim2) s[nt][3] = -1e30f;
            }
        }

        // ---- online softmax (in-warp) ----
        float mx1 = -1e30f, mx2 = -1e30f;
#pragma unroll
        for (int nt = 0; nt < 8; nt++) {
            mx1 = fmaxf(mx1, fmaxf(s[nt][0], s[nt][1]));
            mx2 = fmaxf(mx2, fmaxf(s[nt][2], s[nt][3]));
        }
        mx1 = fmaxf(mx1, __shfl_xor_sync(0xffffffffu, mx1, 1));
        mx1 = fmaxf(mx1, __shfl_xor_sync(0xffffffffu, mx1, 2));
        mx2 = fmaxf(mx2, __shfl_xor_sync(0xffffffffu, mx2, 1));
        mx2 = fmaxf(mx2, __shfl_xor_sync(0xffffffffu, mx2, 2));

        const float mn1 = fmaxf(m1, mx1);
        const float mn2 = fmaxf(m2, mx2);
        const float al1 = __expf(m1 - mn1);
        const float al2 = __expf(m2 - mn2);

        float sm1 = 0.f, sm2 = 0.f;
#pragma unroll
        for (int nt = 0; nt < 8; nt++) {
            s[nt][0] = __expf(s[nt][0] - mn1);
            s[nt][1] = __expf(s[nt][1] - mn1);
            s[nt][2] = __expf(s[nt][2] - mn2);
            s[nt][3] = __expf(s[nt][3] - mn2);
            sm1 += s[nt][0] + s[nt][1];
            sm2 += s[nt][2] + s[nt][3];
        }
        sm1 += __shfl_xor_sync(0xffffffffu, sm1, 1);
        sm1 += __shfl_xor_sync(0xffffffffu, sm1, 2);
        sm2 += __shfl_xor_sync(0xffffffffu, sm2, 1);
        sm2 += __shfl_xor_sync(0xffffffffu, sm2, 2);

        l1 = al1 * l1 + sm1;
        l2 = al2 * l2 + sm2;
        m1 = mn1;
        m2 = mn2;

        // pack P into A-fragment registers (S layout == A layout; no smem)
        uint32_t ph[8], pl[8];
#pragma unroll
        for (int nt = 0; nt < 8; nt++) {
            ph[nt] = packh2(s[nt][0], s[nt][1]);   // row r1
            pl[nt] = packh2(s[nt][2], s[nt][3]);   // row r2
        }

        // rescale O
#pragma unroll
        for (int nt = 0; nt < 16; nt++) {
            o[nt][0] *= al1; o[nt][1] *= al1;
            o[nt][2] *= al2; o[nt][3] *= al2;
        }

        // ---- O += P @ V : warp 16 x 128, kv = 64 (4 x k16), V via trans-ldmatrix ----
        const uint32_t v_lm = v_lm0 + ((j & 1) ? (64u * 272u) : 0u);
#pragma unroll
        for (int ks = 0; ks < 4; ks++) {
            uint32_t af[4] = { ph[2 * ks], pl[2 * ks], ph[2 * ks + 1], pl[2 * ks + 1] };
            const uint32_t vb = v_lm + ks * (16 * 272);
#pragma unroll
            for (int q = 0; q < 8; q++) {     // q = 16-wide d-tile
                uint32_t r0, r1r, r2r, r3;
                LDSM4T(r0, r1r, r2r, r3, vb + q * 32);
                uint32_t bfA[2] = { r0, r1r };   // d-tile 2q   : b0=kv0-7, b1=kv8-15
                uint32_t bfB[2] = { r2r, r3 };   // d-tile 2q+1
                mma16(o[2 * q],     af, bfA);
                mma16(o[2 * q + 1], af, bfB);
            }
        }
    }

    const float inv1 = 1.f / l1;
    const float inv2 = 1.f / l2;
    __half* Og = out + ((size_t)b * SEQ + q0) * D_MODEL + h * D_HEAD;
#pragma unroll
    for (int nt = 0; nt < 16; nt++) {
        int c = nt * 8 + tig * 2;
        *(__half2*)(Og + (size_t)r1 * D_MODEL + c) =
            __floats2half2_rn(o[nt][0] * inv1, o[nt][1] * inv1);
        *(__half2*)(Og + (size_t)r2 * D_MODEL + c) =
            __floats2half2_rn(o[nt][2] * inv2, o[nt][3] * inv2);
    }
}

// ============================================================================
// Launch
// ============================================================================
extern "C" void kernel_launch(void* const* d_in, const int* in_sizes, int n_in,
                              void* d_out, int out_size) {
    const float* x    = (const float*)d_in[0];
    const float* Wqkv = (const float*)d_in[1];
    const float* bqkv = (const float*)d_in[2];
    const float* Wout = (const float*)d_in[3];
    const float* bout = (const float*)d_in[4];
    float* out = (float*)d_out;

    __half *qkv_p, *att_p, *xh_p, *wqkvT_p, *woutT_p;
    cudaGetSymbolAddress((void**)&qkv_p, g_qkv);
    cudaGetSymbolAddress((void**)&att_p, g_att);
    cudaGetSymbolAddress((void**)&xh_p, g_xh);
    cudaGetSymbolAddress((void**)&wqkvT_p, g_wqkvT);
    cudaGetSymbolAddress((void**)&woutT_p, g_woutT);

    cudaFuncSetAttribute(gemm_h, cudaFuncAttributeMaxDynamicSharedMemorySize,
                         (int)G_SMEM_BYTES);
    cudaFuncSetAttribute(attn_kernel, cudaFuncAttributeMaxDynamicSharedMemorySize,
                         (int)ATTN_SMEM_BYTES);

    // Prep: one fused launch (x convert + both weight transposes)
    prep_all<<<NB_PREP, 256>>>(x, xh_p, Wqkv, wqkvT_p, Wout, woutT_p);

    // 1) qkv = x @ W_qkv + b_qkv  [4096, 6144], fp16 out, Q columns pre-scaled
    gemm_h<<<dim3(QKV_N / 128, BS / 128), 256, G_SMEM_BYTES>>>(
        xh_p, wqkvT_p, bqkv, nullptr, qkv_p, BS, QKV_N, D_MODEL, 1);

    // 2) causal flash attention -> g_att (fp16)
    attn_kernel<<<dim3(SEQ / 128, N_HEADS, BATCH), 256, ATTN_SMEM_BYTES>>>(qkv_p, att_p);

    // 3) out = att @ W_out + b_out  [4096, 2048], fp32 out
    gemm_h<<<dim3(D_MODEL / 128, BS / 128), 256, G_SMEM_BYTES>>>(
        att_p, woutT_p, bout, out, nullptr, BS, D_MODEL, D_MODEL, 0);
}